// round 6
// baseline (speedup 1.0000x reference)
#include <cuda_runtime.h>
#include <cuda_bf16.h>
#include <cstdint>

#define NODES 100000
#define EDGES 3200000
#define BN_EPS 1e-5f

// ---------------- scratch (no allocation allowed) ----------------
__device__ float g_h[NODES * 256];                         // fp32 layer output (agg input / head)
__device__ __align__(16) unsigned char g_zh[NODES * 256 * 2];  // z hi plane (bf16)
__device__ __align__(16) unsigned char g_zl[NODES * 256 * 2];  // z lo plane
__device__ __align__(16) unsigned char g_mh[NODES * 256 * 2];  // m hi plane
__device__ __align__(16) unsigned char g_ml[NODES * 256 * 2];  // m lo plane
__device__ int   g_counts[NODES];
__device__ int   g_offsets[NODES];
__device__ int   g_cursor[NODES];
__device__ int   g_blocksums[128];
__device__ int   g_csr[EDGES];
// weight images per GEMM: Bt_hi[256][K] bf16 then Bt_lo[256][K] bf16 (k-major)
__device__ __align__(16) unsigned char g_wimg[6][262144];

// ---------------- helpers ----------------
__device__ __forceinline__ uint32_t smem_u32(const void* p) {
    uint32_t a;
    asm("{ .reg .u64 t; cvta.to.shared.u64 t, %1; cvt.u32.u64 %0, t; }" : "=r"(a) : "l"(p));
    return a;
}
__device__ __forceinline__ void ldsm4(uint32_t* r, uint32_t addr) {
    asm volatile("ldmatrix.sync.aligned.m8n8.x4.shared.b16 {%0,%1,%2,%3}, [%4];"
        : "=r"(r[0]), "=r"(r[1]), "=r"(r[2]), "=r"(r[3]) : "r"(addr));
}
__device__ __forceinline__ void ldsm2(uint32_t* r, uint32_t addr) {
    asm volatile("ldmatrix.sync.aligned.m8n8.x2.shared.b16 {%0,%1}, [%2];"
        : "=r"(r[0]), "=r"(r[1]) : "r"(addr));
}
__device__ __forceinline__ void mma16816(float* d, const uint32_t* a, const uint32_t* b) {
    asm volatile(
        "mma.sync.aligned.m16n8k16.row.col.f32.bf16.bf16.f32 "
        "{%0,%1,%2,%3}, {%4,%5,%6,%7}, {%8,%9}, {%0,%1,%2,%3};"
        : "+f"(d[0]), "+f"(d[1]), "+f"(d[2]), "+f"(d[3])
        : "r"(a[0]), "r"(a[1]), "r"(a[2]), "r"(a[3]), "r"(b[0]), "r"(b[1]));
}
__device__ __forceinline__ void cp16(uint32_t s, const void* g, uint32_t srcsz) {
    asm volatile("cp.async.cg.shared.global [%0], [%1], 16, %2;"
        :: "r"(s), "l"(g), "r"(srcsz));
}
__device__ __forceinline__ void cpcommit() {
    asm volatile("cp.async.commit_group;" ::: "memory");
}
template <int N> __device__ __forceinline__ void cpwait() {
    asm volatile("cp.async.wait_group %0;" :: "n"(N) : "memory");
}
__device__ __forceinline__ void bfsplit(float v, unsigned short& hi, unsigned short& lo) {
    __nv_bfloat16 hb = __float2bfloat16(v);
    __nv_bfloat16 lb = __float2bfloat16(v - __bfloat162float(hb));
    hi = reinterpret_cast<unsigned short&>(hb);
    lo = reinterpret_cast<unsigned short&>(lb);
}

// ---------------- setup: zero counts + prep all 6 weight images ----------------
#define PREP_TOTAL (32768 + 5 * 65536)   // 360448
__global__ void setup_kernel(const float* W0, const float* W1, const float* W2,
                             const float* W3, const float* W4, const float* W5,
                             unsigned char* img) {
    int t = blockIdx.x * blockDim.x + threadIdx.x;
    if (t < NODES) g_counts[t] = 0;
    if (t < PREP_TOTAL) {
        int i, local;
        if (t < 32768) { i = 0; local = t; }
        else { i = 1 + (t - 32768) / 65536; local = (t - 32768) % 65536; }
        int K = (i == 0) ? 128 : 256;
        const float* W = (i == 0) ? W0 : (i == 1) ? W1 : (i == 2) ? W2 :
                         (i == 3) ? W3 : (i == 4) ? W4 : W5;
        int n = local / K, k = local % K;
        float v = W[(size_t)k * 256 + n];
        unsigned short hi, lo;
        bfsplit(v, hi, lo);
        unsigned char* base = img + (size_t)i * 262144;
        ((unsigned short*)base)[n * K + k] = hi;
        ((unsigned short*)(base + (size_t)256 * K * 2))[n * K + k] = lo;
    }
}

// ---------------- CSR build ----------------
__global__ void hist_kernel(const int* __restrict__ dst) {
    int e = blockIdx.x * blockDim.x + threadIdx.x;
    if (e < EDGES) atomicAdd(&g_counts[dst[e]], 1);
}
#define SCAN_CHUNK 1024
#define SCAN_NB ((NODES + SCAN_CHUNK - 1) / SCAN_CHUNK)   // 98
__global__ void scan1_kernel() {
    __shared__ int s[SCAN_CHUNK];
    int t = threadIdx.x;
    int i = blockIdx.x * SCAN_CHUNK + t;
    s[t] = (i < NODES) ? g_counts[i] : 0;
    __syncthreads();
    for (int d = SCAN_CHUNK / 2; d > 0; d >>= 1) {
        if (t < d) s[t] += s[t + d];
        __syncthreads();
    }
    if (t == 0) g_blocksums[blockIdx.x] = s[0];
}
// fused: every block scans the 98 blocksums, then scans its own chunk
__global__ void scan23_kernel() {
    __shared__ int bs[128];
    __shared__ int borig[128];
    __shared__ int s[SCAN_CHUNK];
    int t = threadIdx.x;
    if (t < 128) {
        int v = (t < SCAN_NB) ? g_blocksums[t] : 0;
        bs[t] = v; borig[t] = v;
    }
    __syncthreads();
    for (int d = 1; d < 128; d <<= 1) {
        int x = 0;
        if (t < 128 && t >= d) x = bs[t - d];
        __syncthreads();
        if (t < 128) bs[t] += x;
        __syncthreads();
    }
    int base = bs[blockIdx.x] - borig[blockIdx.x];   // exclusive prefix of blocks

    int i = blockIdx.x * SCAN_CHUNK + t;
    int v = (i < NODES) ? g_counts[i] : 0;
    s[t] = v;
    __syncthreads();
    for (int d = 1; d < SCAN_CHUNK; d <<= 1) {
        int x = (t >= d) ? s[t - d] : 0;
        __syncthreads();
        s[t] += x;
        __syncthreads();
    }
    int off = base + s[t] - v;
    if (i < NODES) {
        g_offsets[i] = off;
        g_cursor[i]  = off;
    }
}
__global__ void scatter_kernel(const int* __restrict__ src, const int* __restrict__ dst) {
    int e = blockIdx.x * blockDim.x + threadIdx.x;
    if (e < EDGES) {
        int d = dst[e];
        int pos = atomicAdd(&g_cursor[d], 1);
        g_csr[pos] = src[e];
    }
}

// ---------------- aggregation: fp32 gather -> bf16 hi/lo planes ----------------
template <int F>
__global__ void agg_kernel(const float* __restrict__ h,
                           unsigned char* __restrict__ zh,
                           unsigned char* __restrict__ zl) {
    constexpr int TPN = F / 4;
    constexpr int NPB = 256 / TPN;
    int node = blockIdx.x * NPB + threadIdx.y;
    if (node >= NODES) return;
    int f4 = threadIdx.x;
    const float4* __restrict__ h4 = (const float4*)h;
    float4 acc = h4[(size_t)node * TPN + f4];
    int beg = g_offsets[node];
    int end = beg + g_counts[node];
    int k = beg;
    for (; k + 1 < end; k += 2) {
        int j0 = g_csr[k], j1 = g_csr[k + 1];
        float4 v0 = __ldg(&h4[(size_t)j0 * TPN + f4]);
        float4 v1 = __ldg(&h4[(size_t)j1 * TPN + f4]);
        acc.x += v0.x + v1.x; acc.y += v0.y + v1.y;
        acc.z += v0.z + v1.z; acc.w += v0.w + v1.w;
    }
    if (k < end) {
        int j = g_csr[k];
        float4 v = __ldg(&h4[(size_t)j * TPN + f4]);
        acc.x += v.x; acc.y += v.y; acc.z += v.z; acc.w += v.w;
    }
    unsigned short h0, h1, h2, h3, l0, l1, l2, l3;
    bfsplit(acc.x, h0, l0); bfsplit(acc.y, h1, l1);
    bfsplit(acc.z, h2, l2); bfsplit(acc.w, h3, l3);
    uint2 hp = make_uint2(((uint32_t)h1 << 16) | h0, ((uint32_t)h3 << 16) | h2);
    uint2 lp = make_uint2(((uint32_t)l1 << 16) | l0, ((uint32_t)l3 << 16) | l2);
    size_t off = ((size_t)node * F + f4 * 4) * 2;
    *(uint2*)(zh + off) = hp;
    *(uint2*)(zl + off) = lp;
}

// ---------------- pipelined tensor-core GEMM ----------------
// C[M,256] = A[M,K] @ W[K,256], bf16x3 split, A/B pre-split bf16 planes.
// CTA 128x128, 8 warps (4M x 2N), K chunk 32, 2-stage cp.async double buffer.
// smem rows padded to 80B (conflict-free ldmatrix).
#define AROW 80
#define TILEB (128 * AROW)           // 10240
#define STAGEB (4 * TILEB)           // 40960
#define GEMM_SMEM (1024 + 2 * STAGEB)

__global__ void __launch_bounds__(256, 2) gemm_mma(
    const unsigned char* __restrict__ Ah, const unsigned char* __restrict__ Al,
    const unsigned char* __restrict__ img, int K,
    float* __restrict__ Cf, unsigned char* __restrict__ mh, unsigned char* __restrict__ ml,
    const float* __restrict__ bias, const float* __restrict__ gamma,
    const float* __restrict__ beta, const float* __restrict__ mu,
    const float* __restrict__ var, int mode)
{
    extern __shared__ __align__(16) unsigned char dynsmem[];
    float* s_sc = (float*)dynsmem;
    float* s_sh = (float*)(dynsmem + 512);
    unsigned char* stg = dynsmem + 1024;

    int tid = threadIdx.x;
    int wid = tid >> 5, lane = tid & 31;
    int wm = wid & 3, wn = wid >> 2;
    int m0 = blockIdx.x * 128;
    int bn = blockIdx.y;

    const unsigned char* imgh = img;
    const unsigned char* imgl = img + (size_t)256 * K * 2;

    if (tid < 128) {
        int col = bn * 128 + tid;
        float s, h;
        if (mode == 0) {
            s = gamma[col] * rsqrtf(var[col] + BN_EPS);
            h = beta[col] + (bias[col] - mu[col]) * s;
        } else {
            s = 1.f;
            h = bias[col];
        }
        s_sc[tid] = s;
        s_sh[tid] = h;
    }

    float acc[2][8][4];
#pragma unroll
    for (int i = 0; i < 2; i++)
#pragma unroll
        for (int j = 0; j < 8; j++)
#pragma unroll
            for (int q = 0; q < 4; q++) acc[i][j][q] = 0.f;

    // per-thread copy coords: 512 16B pieces per tile -> 2 per thread
    int row_c[2], q_c[2];
#pragma unroll
    for (int i = 0; i < 2; i++) {
        int idx = tid + i * 256;
        row_c[i] = idx >> 2;
        q_c[i] = idx & 3;
    }

    uint32_t stg_b = smem_u32(stg);
    int nchunk = K >> 5;

    // ldmatrix per-lane base offsets
    int l16 = lane & 15;
    uint32_t a_off = (uint32_t)((wm * 32 + l16) * AROW + (lane >> 4) * 16);
    uint32_t b_off = (uint32_t)((wn * 64 + (l16 & 7)) * AROW + ((l16 >> 3) & 1) * 16);

    auto issue_copy = [&](int c, int s) {
        uint32_t sb = stg_b + s * STAGEB;
#pragma unroll
        for (int i = 0; i < 2; i++) {
            int row = row_c[i], q = q_c[i];
            uint32_t so = (uint32_t)(row * AROW + q * 16);
            int grow = m0 + row;
            uint32_t ssz = (grow < NODES) ? 16u : 0u;
            size_t aoff = ((size_t)grow * K + c * 32) * 2 + q * 16;
            cp16(sb + so,             Ah + aoff, ssz);
            cp16(sb + TILEB + so,     Al + aoff, ssz);
            size_t boff = ((size_t)(bn * 128 + row) * K + c * 32) * 2 + q * 16;
            cp16(sb + 2 * TILEB + so, imgh + boff, 16u);
            cp16(sb + 3 * TILEB + so, imgl + boff, 16u);
        }
        cpcommit();
    };

    issue_copy(0, 0);
    for (int c = 0; c < nchunk; c++) {
        int s = c & 1;
        if (c + 1 < nchunk) {
            issue_copy(c + 1, s ^ 1);
            cpwait<1>();
        } else {
            cpwait<0>();
        }
        __syncthreads();

        uint32_t ah_b = stg_b + s * STAGEB;
        uint32_t al_b = ah_b + TILEB;
        uint32_t bh_b = ah_b + 2 * TILEB;
        uint32_t bl_b = ah_b + 3 * TILEB;
#pragma unroll
        for (int ks = 0; ks < 2; ks++) {
            uint32_t a_hi[2][4], a_lo[2][4];
#pragma unroll
            for (int mt = 0; mt < 2; mt++) {
                ldsm4(a_hi[mt], ah_b + a_off + mt * 16 * AROW + ks * 32);
                ldsm4(a_lo[mt], al_b + a_off + mt * 16 * AROW + ks * 32);
            }
#pragma unroll
            for (int nh = 0; nh < 2; nh++) {
                uint32_t b_hi[4][2], b_lo[4][2];
#pragma unroll
                for (int t4 = 0; t4 < 4; t4++) {
                    int nt = nh * 4 + t4;
                    ldsm2(b_hi[t4], bh_b + b_off + nt * 8 * AROW + ks * 32);
                    ldsm2(b_lo[t4], bl_b + b_off + nt * 8 * AROW + ks * 32);
                }
#pragma unroll
                for (int mt = 0; mt < 2; mt++)
#pragma unroll
                    for (int t4 = 0; t4 < 4; t4++) {
                        int nt = nh * 4 + t4;
                        mma16816(acc[mt][nt], a_hi[mt], b_hi[t4]);
                        mma16816(acc[mt][nt], a_lo[mt], b_hi[t4]);
                        mma16816(acc[mt][nt], a_hi[mt], b_lo[t4]);
                    }
            }
        }
        __syncthreads();
    }

    // ---- epilogue ----
#pragma unroll
    for (int mt = 0; mt < 2; mt++) {
        int row0 = m0 + wm * 32 + mt * 16 + (lane >> 2);
#pragma unroll
        for (int nt = 0; nt < 8; nt++) {
            int colL = wn * 64 + nt * 8 + (lane & 3) * 2;
            float sc0 = s_sc[colL], sc1 = s_sc[colL + 1];
            float sh0 = s_sh[colL], sh1 = s_sh[colL + 1];
            float v0 = acc[mt][nt][0] * sc0 + sh0;
            float v1 = acc[mt][nt][1] * sc1 + sh1;
            float v2 = acc[mt][nt][2] * sc0 + sh0;
            float v3 = acc[mt][nt][3] * sc1 + sh1;
            if (mode < 2) {
                v0 = fmaxf(v0, 0.f); v1 = fmaxf(v1, 0.f);
                v2 = fmaxf(v2, 0.f); v3 = fmaxf(v3, 0.f);
            }
            int colG = bn * 128 + colL;
            if (mode == 0) {
                unsigned short h0, h1, l0, l1;
                if (row0 < NODES) {
                    bfsplit(v0, h0, l0); bfsplit(v1, h1, l1);
                    size_t off = ((size_t)row0 * 256 + colG) * 2;
                    *(uint32_t*)(mh + off) = ((uint32_t)h1 << 16) | h0;
                    *(uint32_t*)(ml + off) = ((uint32_t)l1 << 16) | l0;
                }
                if (row0 + 8 < NODES) {
                    bfsplit(v2, h0, l0); bfsplit(v3, h1, l1);
                    size_t off = ((size_t)(row0 + 8) * 256 + colG) * 2;
                    *(uint32_t*)(mh + off) = ((uint32_t)h1 << 16) | h0;
                    *(uint32_t*)(ml + off) = ((uint32_t)l1 << 16) | l0;
                }
            } else {
                if (row0 < NODES)
                    *(float2*)&Cf[(size_t)row0 * 256 + colG] = make_float2(v0, v1);
                if (row0 + 8 < NODES)
                    *(float2*)&Cf[(size_t)(row0 + 8) * 256 + colG] = make_float2(v2, v3);
            }
        }
    }
}

// ---------------- output head ----------------
__global__ void out_kernel(const float* __restrict__ h, const float* __restrict__ W,
                           const float* __restrict__ b, float* __restrict__ out) {
    int gw = (blockIdx.x * blockDim.x + threadIdx.x) >> 5;
    int lane = threadIdx.x & 31;
    if (gw >= NODES) return;
    const float* row = h + (size_t)gw * 256;
    float a0 = 0.f, a1 = 0.f;
    for (int k = lane; k < 256; k += 32) {
        float v = row[k];
        a0 += v * W[k * 2];
        a1 += v * W[k * 2 + 1];
    }
#pragma unroll
    for (int o = 16; o > 0; o >>= 1) {
        a0 += __shfl_down_sync(0xFFFFFFFFu, a0, o);
        a1 += __shfl_down_sync(0xFFFFFFFFu, a1, o);
    }
    if (lane == 0) {
        out[gw * 2]     = a0 + b[0];
        out[gw * 2 + 1] = a1 + b[1];
    }
}

// ---------------- launch ----------------
extern "C" void kernel_launch(void* const* d_in, const int* in_sizes, int n_in,
                              void* d_out, int out_size) {
    const float* x   = (const float*)d_in[0];
    const int*   ei  = (const int*)d_in[1];
    const int*   src = ei;
    const int*   dst = ei + EDGES;

    const float* L[3][8];
    for (int l = 0; l < 3; l++)
        for (int p = 0; p < 8; p++)
            L[l][p] = (const float*)d_in[2 + l * 8 + p];
    const float* out_W = (const float*)d_in[26];
    const float* out_b = (const float*)d_in[27];
    float* out = (float*)d_out;

    float* hp; cudaGetSymbolAddress((void**)&hp, g_h);
    unsigned char* zh; cudaGetSymbolAddress((void**)&zh, g_zh);
    unsigned char* zl; cudaGetSymbolAddress((void**)&zl, g_zl);
    unsigned char* mh; cudaGetSymbolAddress((void**)&mh, g_mh);
    unsigned char* ml; cudaGetSymbolAddress((void**)&ml, g_ml);
    unsigned char* wimg; cudaGetSymbolAddress((void**)&wimg, g_wimg);

    cudaFuncSetAttribute(gemm_mma, cudaFuncAttributeMaxDynamicSharedMemorySize, GEMM_SMEM);

    // setup: zero counts + all weight images
    setup_kernel<<<(PREP_TOTAL + 255) / 256, 256>>>(
        L[0][0], L[0][6], L[1][0], L[1][6], L[2][0], L[2][6], wimg);
    // CSR build
    hist_kernel<<<(EDGES + 255) / 256, 256>>>(dst);
    scan1_kernel<<<SCAN_NB, SCAN_CHUNK>>>();
    scan23_kernel<<<SCAN_NB, SCAN_CHUNK>>>();
    scatter_kernel<<<(EDGES + 255) / 256, 256>>>(src, dst);

    dim3 ggrid((NODES + 127) / 128, 2);

    // layer 1 (K=128 for gemm1)
    agg_kernel<128><<<(NODES + 7) / 8, dim3(32, 8)>>>(x, zh, zl);
    gemm_mma<<<ggrid, 256, GEMM_SMEM>>>(zh, zl, wimg + 0 * 262144, 128,
        nullptr, mh, ml, L[0][1], L[0][2], L[0][3], L[0][4], L[0][5], 0);
    gemm_mma<<<ggrid, 256, GEMM_SMEM>>>(mh, ml, wimg + 1 * 262144, 256,
        hp, nullptr, nullptr, L[0][7], nullptr, nullptr, nullptr, nullptr, 1);
    // layer 2
    agg_kernel<256><<<(NODES + 3) / 4, dim3(64, 4)>>>(hp, zh, zl);
    gemm_mma<<<ggrid, 256, GEMM_SMEM>>>(zh, zl, wimg + 2 * 262144, 256,
        nullptr, mh, ml, L[1][1], L[1][2], L[1][3], L[1][4], L[1][5], 0);
    gemm_mma<<<ggrid, 256, GEMM_SMEM>>>(mh, ml, wimg + 3 * 262144, 256,
        hp, nullptr, nullptr, L[1][7], nullptr, nullptr, nullptr, nullptr, 1);
    // layer 3
    agg_kernel<256><<<(NODES + 3) / 4, dim3(64, 4)>>>(hp, zh, zl);
    gemm_mma<<<ggrid, 256, GEMM_SMEM>>>(zh, zl, wimg + 4 * 262144, 256,
        nullptr, mh, ml, L[2][1], L[2][2], L[2][3], L[2][4], L[2][5], 0);
    gemm_mma<<<ggrid, 256, GEMM_SMEM>>>(mh, ml, wimg + 5 * 262144, 256,
        hp, nullptr, nullptr, L[2][7], nullptr, nullptr, nullptr, nullptr, 2);

    // output head
    out_kernel<<<(NODES * 32 + 255) / 256, 256>>>(hp, out_W, out_b, out);
}